// round 1
// baseline (speedup 1.0000x reference)
#include <cuda_runtime.h>
#include <cuda_bf16.h>

#define NN 100000
#define NE 1600000
#define F 64
#define G 64
#define EPS 1e-5f

// ---------------- scratch (device globals; no allocation allowed) ----------
__device__ float g_deg[NN];
__device__ float g_dis[NN];
__device__ float g_norm[NE];
__device__ float g_h1[NN * F];
__device__ float g_h2[NN * F];
__device__ float g_h3[NN * F];
__device__ float g_out[NN * F];
__device__ float g_sum[G * F];
__device__ float g_sumsq[G * F];
__device__ float g_cnt[G];
__device__ float g_scale[G * F];
__device__ float g_shift[G * F];
__device__ float g_psum[G * F];
__device__ float g_pmax[G * F];   // float bits, max via int atomicMax (vals >= 0)

// ---------------- zero scratch ---------------------------------------------
__global__ void k_zero() {
    int i = blockIdx.x * blockDim.x + threadIdx.x;
    int st = gridDim.x * blockDim.x;
    for (int j = i; j < NN * F; j += st) { g_h1[j] = 0.f; g_h2[j] = 0.f; g_h3[j] = 0.f; }
    for (int j = i; j < NN; j += st) g_deg[j] = 0.f;
    for (int j = i; j < G * F; j += st) { g_sum[j] = 0.f; g_sumsq[j] = 0.f; g_psum[j] = 0.f; g_pmax[j] = 0.f; }
    for (int j = i; j < G; j += st) g_cnt[j] = 0.f;
}

// ---------------- degree / norm --------------------------------------------
__global__ void k_deg(const int* __restrict__ dst, const float* __restrict__ w) {
    int e = blockIdx.x * blockDim.x + threadIdx.x;
    if (e < NE) atomicAdd(&g_deg[dst[e]], w[e]);
}

__global__ void k_dis() {
    int n = blockIdx.x * blockDim.x + threadIdx.x;
    if (n < NN) {
        float d = g_deg[n];
        g_dis[n] = d > 0.f ? rsqrtf(d) : 0.f;
    }
}

__global__ void k_norm(const int* __restrict__ src, const int* __restrict__ dst,
                       const float* __restrict__ w) {
    int e = blockIdx.x * blockDim.x + threadIdx.x;
    if (e < NE) g_norm[e] = g_dis[src[e]] * w[e] * g_dis[dst[e]];
}

// ---------------- one propagation hop: hcur[dst] += norm * hprev[src] ------
// 16 lanes per edge, one float4 per lane (row = 64 floats = 16 float4)
__global__ void k_prop(const float* __restrict__ hprev, float* __restrict__ hcur,
                       const int* __restrict__ src, const int* __restrict__ dst) {
    int gid = blockIdx.x * blockDim.x + threadIdx.x;
    int e = gid >> 4;
    int q = gid & 15;
    if (e >= NE) return;
    int s = src[e];
    int d = dst[e];
    float w = g_norm[e];
    float4 v = reinterpret_cast<const float4*>(hprev)[s * 16 + q];
    v.x *= w; v.y *= w; v.z *= w; v.w *= w;
    atomicAdd(reinterpret_cast<float4*>(hcur) + d * 16 + q, v);
}

// ---------------- fused pair matmul: out (=|+=) A@WA + B@WB (+ bias) -------
#define MAT_ROWS 64
__global__ void k_mat2(const float* __restrict__ A, const float* __restrict__ B,
                       const float* __restrict__ WA, const float* __restrict__ WB,
                       const float* __restrict__ bias, float* __restrict__ out,
                       int accumulate) {
    __shared__ float sWA[64 * 64];
    __shared__ float sWB[64 * 64];
    __shared__ float sA[4 * 64];
    __shared__ float sB[4 * 64];
    int tid = threadIdx.x;                 // 256 threads
    for (int i = tid; i < 4096; i += 256) { sWA[i] = WA[i]; sWB[i] = WB[i]; }
    int f = tid & 63;
    int r = tid >> 6;                      // 0..3
    int base = blockIdx.x * MAT_ROWS;
    for (int rr = 0; rr < MAT_ROWS; rr += 4) {
        int row = base + rr + r;
        __syncthreads();
        if (row < NN) {
            sA[r * 64 + f] = A[row * 64 + f];
            sB[r * 64 + f] = B[row * 64 + f];
        }
        __syncthreads();
        if (row < NN) {
            float acc = accumulate ? out[row * 64 + f] : bias[f];
            #pragma unroll
            for (int k = 0; k < 64; k++) {
                acc = fmaf(sA[r * 64 + k], sWA[k * 64 + f], acc);
                acc = fmaf(sB[r * 64 + k], sWB[k * 64 + f], acc);
            }
            out[row * 64 + f] = acc;
        }
    }
}

// ---------------- GraphNorm stats: per-graph sum, sumsq, count --------------
// block = 256 contiguous rows; thread (f, rg) covers rows rg, rg+4, ...
// batch is sorted -> run-length batching of atomics.
__global__ void k_stats(const float* __restrict__ out, const int* __restrict__ batch) {
    int f = threadIdx.x & 63;
    int rg = threadIdx.x >> 6;
    int row0 = blockIdx.x * 256;
    int rend = min(row0 + 256, NN);
    float s = 0.f, sq = 0.f, c = 0.f;
    int curg = -1;
    for (int r = row0 + rg; r < rend; r += 4) {
        int g = batch[r];
        if (g != curg) {
            if (curg >= 0) {
                atomicAdd(&g_sum[curg * 64 + f], s);
                atomicAdd(&g_sumsq[curg * 64 + f], sq);
                if (f == 0) atomicAdd(&g_cnt[curg], c);
            }
            curg = g; s = 0.f; sq = 0.f; c = 0.f;
        }
        float v = out[r * 64 + f];
        s += v; sq += v * v; c += 1.f;
    }
    if (curg >= 0) {
        atomicAdd(&g_sum[curg * 64 + f], s);
        atomicAdd(&g_sumsq[curg * 64 + f], sq);
        if (f == 0) atomicAdd(&g_cnt[curg], c);
    }
}

// ---------------- per-(g,f) scale/shift -------------------------------------
// centered = out - m*ms ;  var = E[o^2] - m^2*ms*(2 - ms)
__global__ void k_prep(const float* __restrict__ gn_w, const float* __restrict__ gn_b,
                       const float* __restrict__ gn_ms) {
    int idx = blockIdx.x * blockDim.x + threadIdx.x;
    if (idx >= G * F) return;
    int g = idx >> 6, f = idx & 63;
    float cnt = fmaxf(g_cnt[g], 1.f);
    float m = g_sum[idx] / cnt;
    float ms = m * gn_ms[f];
    float var = g_sumsq[idx] / cnt - ms * (2.f * m - ms);
    var = fmaxf(var, 0.f);
    float sc = gn_w[f] * rsqrtf(var + EPS);
    g_scale[idx] = sc;
    g_shift[idx] = gn_b[f] - ms * sc;
}

// ---------------- normalize + residual + relu + pooling ---------------------
__global__ void k_final(const float* __restrict__ out, const float* __restrict__ x,
                        const int* __restrict__ batch, float* __restrict__ demb) {
    int f = threadIdx.x & 63;
    int rg = threadIdx.x >> 6;
    int row0 = blockIdx.x * 256;
    int rend = min(row0 + 256, NN);
    float s = 0.f, mx = 0.f;
    int curg = -1;
    float sc = 0.f, sh = 0.f;
    for (int r = row0 + rg; r < rend; r += 4) {
        int g = batch[r];
        if (g != curg) {
            if (curg >= 0) {
                atomicAdd(&g_psum[curg * 64 + f], s);
                atomicMax(reinterpret_cast<int*>(&g_pmax[curg * 64 + f]), __float_as_int(mx));
            }
            curg = g; s = 0.f; mx = 0.f;
            sc = g_scale[g * 64 + f];
            sh = g_shift[g * 64 + f];
        }
        float v = out[r * 64 + f] * sc + sh + x[r * 64 + f];
        v = fmaxf(v, 0.f);
        demb[r * 64 + f] = v;
        s += v;
        mx = fmaxf(mx, v);
    }
    if (curg >= 0) {
        atomicAdd(&g_psum[curg * 64 + f], s);
        atomicMax(reinterpret_cast<int*>(&g_pmax[curg * 64 + f]), __float_as_int(mx));
    }
}

// ---------------- flat output: [G, 2F] = [mean_pool | max_pool] -------------
__global__ void k_flat(float* __restrict__ flat) {
    int idx = blockIdx.x * blockDim.x + threadIdx.x;
    if (idx >= G * 2 * F) return;
    int g = idx >> 7, j = idx & 127;
    float cnt = fmaxf(g_cnt[g], 1.f);
    flat[idx] = (j < 64) ? (g_psum[g * 64 + j] / cnt) : g_pmax[g * 64 + (j - 64)];
}

// ---------------- launch -----------------------------------------------------
extern "C" void kernel_launch(void* const* d_in, const int* in_sizes, int n_in,
                              void* d_out, int out_size) {
    const float* x    = (const float*)d_in[0];       // [NN, F]
    const int*   ei   = (const int*)d_in[1];         // [2, NE]: src=ei, dst=ei+NE
    const int*   batch= (const int*)d_in[2];         // [NN]
    const float* ew   = (const float*)d_in[3];       // [NE]
    const float* W    = (const float*)d_in[4];       // [4, 64, 64]
    const float* bias = (const float*)d_in[5];       // [64]
    const float* gn_w = (const float*)d_in[6];
    const float* gn_b = (const float*)d_in[7];
    const float* gn_ms= (const float*)d_in[8];

    float* demb = (float*)d_out;                     // [NN*F]
    float* flat = (float*)d_out + (size_t)NN * F;    // [G*2F]

    const int* src = ei;
    const int* dst = ei + NE;

    // device-global pointers for kernels taking raw pointers
    float *ph1, *ph2, *ph3, *pout;
    cudaGetSymbolAddress((void**)&ph1, g_h1);
    cudaGetSymbolAddress((void**)&ph2, g_h2);
    cudaGetSymbolAddress((void**)&ph3, g_h3);
    cudaGetSymbolAddress((void**)&pout, g_out);

    k_zero<<<2048, 256>>>();
    k_deg<<<(NE + 255) / 256, 256>>>(dst, ew);
    k_dis<<<(NN + 255) / 256, 256>>>();
    k_norm<<<(NE + 255) / 256, 256>>>(src, dst, ew);

    // 3 hops: x -> h1 -> h2 -> h3 (16 threads/edge)
    int prop_blocks = (NE * 16) / 256;   // 100000, exact
    k_prop<<<prop_blocks, 256>>>(x,   ph1, src, dst);
    k_prop<<<prop_blocks, 256>>>(ph1, ph2, src, dst);
    k_prop<<<prop_blocks, 256>>>(ph2, ph3, src, dst);

    // out = x@W0 + h1@W1 + b ; out += h2@W2 + h3@W3
    int mat_blocks = (NN + MAT_ROWS - 1) / MAT_ROWS;
    k_mat2<<<mat_blocks, 256>>>(x,   ph1, W,            W + 4096,  bias, pout, 0);
    k_mat2<<<mat_blocks, 256>>>(ph2, ph3, W + 2 * 4096, W + 3 * 4096, bias, pout, 1);

    int row_blocks = (NN + 255) / 256;
    k_stats<<<row_blocks, 256>>>(pout, batch);
    k_prep<<<(G * F + 255) / 256, 256>>>(gn_w, gn_b, gn_ms);
    k_final<<<row_blocks, 256>>>(pout, x, batch, demb);
    k_flat<<<(G * 2 * F + 255) / 256, 256>>>(flat);
}

// round 2
// speedup vs baseline: 1.3630x; 1.3630x over previous
#include <cuda_runtime.h>
#include <cuda_bf16.h>

#define NN 100000
#define NE 1600000
#define F 64
#define G 64
#define EPS 1e-5f
#define SCAN_B 512
#define NSCB ((NN + SCAN_B - 1) / SCAN_B)   // 196

// ---------------- scratch (device globals) ----------------------------------
__device__ float g_deg[NN];
__device__ float g_dis[NN];
__device__ int   g_count[NN];
__device__ int   g_scan[NN];
__device__ int   g_rowstart[NN];
__device__ int   g_cursor[NN];
__device__ int   g_bsum[NSCB];
__device__ int   g_boff[NSCB];
__device__ unsigned long long g_csr[NE];   // low32 = src idx, high32 = norm bits
__device__ float g_h1[NN * F];
__device__ float g_h2[NN * F];
__device__ float g_h3[NN * F];
__device__ float g_out[NN * F];
__device__ float g_sum[G * F];
__device__ float g_sumsq[G * F];
__device__ float g_cnt[G];
__device__ float g_scale[G * F];
__device__ float g_shift[G * F];
__device__ float g_psum[G * F];
__device__ float g_pmax[G * F];

// ---------------- zero small scratch ----------------------------------------
__global__ void k_zero() {
    int i = blockIdx.x * blockDim.x + threadIdx.x;
    int st = gridDim.x * blockDim.x;
    for (int j = i; j < NN; j += st) { g_deg[j] = 0.f; g_count[j] = 0; }
    for (int j = i; j < G * F; j += st) { g_sum[j] = 0.f; g_sumsq[j] = 0.f; g_psum[j] = 0.f; g_pmax[j] = 0.f; }
    for (int j = i; j < G; j += st) g_cnt[j] = 0.f;
}

// ---------------- weighted degree + in-degree count --------------------------
__global__ void k_deg(const int* __restrict__ dst, const float* __restrict__ w) {
    int e = blockIdx.x * blockDim.x + threadIdx.x;
    if (e < NE) {
        int d = dst[e];
        atomicAdd(&g_deg[d], w[e]);
        atomicAdd(&g_count[d], 1);
    }
}

__global__ void k_dis() {
    int n = blockIdx.x * blockDim.x + threadIdx.x;
    if (n < NN) {
        float d = g_deg[n];
        g_dis[n] = d > 0.f ? rsqrtf(d) : 0.f;
    }
}

// ---------------- prefix scan of counts (3 kernels) --------------------------
__global__ void k_scan1() {
    __shared__ int s[SCAN_B];
    int tid = threadIdx.x;
    int i = blockIdx.x * SCAN_B + tid;
    int v = (i < NN) ? g_count[i] : 0;
    s[tid] = v;
    __syncthreads();
    for (int off = 1; off < SCAN_B; off <<= 1) {
        int t = (tid >= off) ? s[tid - off] : 0;
        __syncthreads();
        s[tid] += t;
        __syncthreads();
    }
    if (i < NN) g_scan[i] = s[tid] - v;       // exclusive
    if (tid == SCAN_B - 1) g_bsum[blockIdx.x] = s[tid];
}

__global__ void k_scan2() {
    __shared__ int s[256];
    int tid = threadIdx.x;
    int v = (tid < NSCB) ? g_bsum[tid] : 0;
    s[tid] = v;
    __syncthreads();
    for (int off = 1; off < 256; off <<= 1) {
        int t = (tid >= off) ? s[tid - off] : 0;
        __syncthreads();
        s[tid] += t;
        __syncthreads();
    }
    if (tid < NSCB) g_boff[tid] = s[tid] - v; // exclusive
}

__global__ void k_scan3() {
    int i = blockIdx.x * blockDim.x + threadIdx.x;
    if (i < NN) {
        int v = g_scan[i] + g_boff[i >> 9];
        g_rowstart[i] = v;
        g_cursor[i] = v;
    }
}

// ---------------- scatter edges into CSR with fused norm ---------------------
__global__ void k_scatter(const int* __restrict__ src, const int* __restrict__ dst,
                          const float* __restrict__ w) {
    int e = blockIdx.x * blockDim.x + threadIdx.x;
    if (e >= NE) return;
    int s = src[e];
    int d = dst[e];
    float nw = g_dis[s] * w[e] * g_dis[d];
    int p = atomicAdd(&g_cursor[d], 1);
    g_csr[p] = ((unsigned long long)__float_as_uint(nw) << 32) | (unsigned)s;
}

// ---------------- gather hop: hcur[n] = sum_e norm_e * hprev[src_e] ----------
// 16 threads per node, one float4 lane each. Unroll 4 for MLP.
__global__ void k_gather(const float4* __restrict__ hprev, float4* __restrict__ hcur) {
    int gid = blockIdx.x * blockDim.x + threadIdx.x;
    int n = gid >> 4;
    int q = gid & 15;
    if (n >= NN) return;
    int e = g_rowstart[n];
    int end = e + g_count[n];
    float4 acc = make_float4(0.f, 0.f, 0.f, 0.f);
    for (; e + 4 <= end; e += 4) {
        unsigned long long r0 = g_csr[e];
        unsigned long long r1 = g_csr[e + 1];
        unsigned long long r2 = g_csr[e + 2];
        unsigned long long r3 = g_csr[e + 3];
        float4 v0 = hprev[(int)(r0 & 0xffffffffu) * 16 + q];
        float4 v1 = hprev[(int)(r1 & 0xffffffffu) * 16 + q];
        float4 v2 = hprev[(int)(r2 & 0xffffffffu) * 16 + q];
        float4 v3 = hprev[(int)(r3 & 0xffffffffu) * 16 + q];
        float w0 = __uint_as_float((unsigned)(r0 >> 32));
        float w1 = __uint_as_float((unsigned)(r1 >> 32));
        float w2 = __uint_as_float((unsigned)(r2 >> 32));
        float w3 = __uint_as_float((unsigned)(r3 >> 32));
        acc.x = fmaf(w0, v0.x, acc.x); acc.y = fmaf(w0, v0.y, acc.y);
        acc.z = fmaf(w0, v0.z, acc.z); acc.w = fmaf(w0, v0.w, acc.w);
        acc.x = fmaf(w1, v1.x, acc.x); acc.y = fmaf(w1, v1.y, acc.y);
        acc.z = fmaf(w1, v1.z, acc.z); acc.w = fmaf(w1, v1.w, acc.w);
        acc.x = fmaf(w2, v2.x, acc.x); acc.y = fmaf(w2, v2.y, acc.y);
        acc.z = fmaf(w2, v2.z, acc.z); acc.w = fmaf(w2, v2.w, acc.w);
        acc.x = fmaf(w3, v3.x, acc.x); acc.y = fmaf(w3, v3.y, acc.y);
        acc.z = fmaf(w3, v3.z, acc.z); acc.w = fmaf(w3, v3.w, acc.w);
    }
    for (; e < end; e++) {
        unsigned long long r0 = g_csr[e];
        float4 v0 = hprev[(int)(r0 & 0xffffffffu) * 16 + q];
        float w0 = __uint_as_float((unsigned)(r0 >> 32));
        acc.x = fmaf(w0, v0.x, acc.x); acc.y = fmaf(w0, v0.y, acc.y);
        acc.z = fmaf(w0, v0.z, acc.z); acc.w = fmaf(w0, v0.w, acc.w);
    }
    hcur[n * 16 + q] = acc;
}

// ---------------- fused 4-way matmul: out = b + sum_m X_m @ W_m --------------
// dyn smem: sW[4][64][64] (65536B) + sX[4][16][68] (17408B) = 82944B
#define SX_STRIDE 68
__global__ void __launch_bounds__(256) k_mat4(
        const float* __restrict__ X0, const float* __restrict__ X1,
        const float* __restrict__ X2, const float* __restrict__ X3,
        const float* __restrict__ W, const float* __restrict__ bias,
        float* __restrict__ out) {
    extern __shared__ float sm[];
    float* sW = sm;                       // 4*4096 floats
    float* sX = sm + 4 * 4096;            // 4*16*68 floats
    int tid = threadIdx.x;
    // load 4 weight matrices (4096 float4)
    const float4* W4 = (const float4*)W;
    float4* sW4 = (float4*)sW;
    for (int i = tid; i < 4096; i += 256) sW4[i] = W4[i];

    int f4 = tid & 15;          // float4 column index
    int r  = tid >> 4;          // 0..15 (staging row) ; compute uses rows r&7 and (r&7)+8
    int rc = r & 7;
    int base = blockIdx.x * 64;
    const float* Xs[4] = {X0, X1, X2, X3};

    float4 bv = ((const float4*)bias)[f4];

    for (int c = 0; c < 4; c++) {
        int row_st = base + c * 16 + r;
        __syncthreads();
        if (row_st < NN) {
            #pragma unroll
            for (int m = 0; m < 4; m++)
                ((float4*)sX)[(m * 16 + r) * (SX_STRIDE / 4) + f4] =
                    ((const float4*)Xs[m])[row_st * 16 + f4];
        }
        __syncthreads();
        int rowA = base + c * 16 + rc;
        int rowB = rowA + 8;
        float4 accA = bv, accB = bv;
        #pragma unroll 8
        for (int k = 0; k < 64; k++) {
            #pragma unroll
            for (int m = 0; m < 4; m++) {
                float4 wv = ((float4*)sW)[m * 1024 + k * 16 + f4];
                float aA = sX[(m * 16 + rc) * SX_STRIDE + k];
                float aB = sX[(m * 16 + rc + 8) * SX_STRIDE + k];
                accA.x = fmaf(aA, wv.x, accA.x); accA.y = fmaf(aA, wv.y, accA.y);
                accA.z = fmaf(aA, wv.z, accA.z); accA.w = fmaf(aA, wv.w, accA.w);
                accB.x = fmaf(aB, wv.x, accB.x); accB.y = fmaf(aB, wv.y, accB.y);
                accB.z = fmaf(aB, wv.z, accB.z); accB.w = fmaf(aB, wv.w, accB.w);
            }
        }
        if (r < 8) {
            if (rowA < NN) ((float4*)out)[rowA * 16 + f4] = accA;
        } else {
            if (rowB < NN) ((float4*)out)[rowB * 16 + f4] = accB;
        }
    }
}

// ---------------- GraphNorm stats --------------------------------------------
__global__ void k_stats(const float* __restrict__ out, const int* __restrict__ batch) {
    int f = threadIdx.x & 63;
    int rg = threadIdx.x >> 6;
    int row0 = blockIdx.x * 256;
    int rend = min(row0 + 256, NN);
    float s = 0.f, sq = 0.f, c = 0.f;
    int curg = -1;
    for (int r = row0 + rg; r < rend; r += 4) {
        int g = batch[r];
        if (g != curg) {
            if (curg >= 0) {
                atomicAdd(&g_sum[curg * 64 + f], s);
                atomicAdd(&g_sumsq[curg * 64 + f], sq);
                if (f == 0) atomicAdd(&g_cnt[curg], c);
            }
            curg = g; s = 0.f; sq = 0.f; c = 0.f;
        }
        float v = out[r * 64 + f];
        s += v; sq += v * v; c += 1.f;
    }
    if (curg >= 0) {
        atomicAdd(&g_sum[curg * 64 + f], s);
        atomicAdd(&g_sumsq[curg * 64 + f], sq);
        if (f == 0) atomicAdd(&g_cnt[curg], c);
    }
}

// ---------------- per-(g,f) scale/shift ---------------------------------------
__global__ void k_prep(const float* __restrict__ gn_w, const float* __restrict__ gn_b,
                       const float* __restrict__ gn_ms) {
    int idx = blockIdx.x * blockDim.x + threadIdx.x;
    if (idx >= G * F) return;
    int g = idx >> 6, f = idx & 63;
    float cnt = fmaxf(g_cnt[g], 1.f);
    float m = g_sum[idx] / cnt;
    float ms = m * gn_ms[f];
    float var = g_sumsq[idx] / cnt - ms * (2.f * m - ms);
    var = fmaxf(var, 0.f);
    float sc = gn_w[f] * rsqrtf(var + EPS);
    g_scale[idx] = sc;
    g_shift[idx] = gn_b[f] - ms * sc;
}

// ---------------- normalize + residual + relu + pooling -----------------------
__global__ void k_final(const float* __restrict__ out, const float* __restrict__ x,
                        const int* __restrict__ batch, float* __restrict__ demb) {
    int f = threadIdx.x & 63;
    int rg = threadIdx.x >> 6;
    int row0 = blockIdx.x * 256;
    int rend = min(row0 + 256, NN);
    float s = 0.f, mx = 0.f;
    int curg = -1;
    float sc = 0.f, sh = 0.f;
    for (int r = row0 + rg; r < rend; r += 4) {
        int g = batch[r];
        if (g != curg) {
            if (curg >= 0) {
                atomicAdd(&g_psum[curg * 64 + f], s);
                atomicMax(reinterpret_cast<int*>(&g_pmax[curg * 64 + f]), __float_as_int(mx));
            }
            curg = g; s = 0.f; mx = 0.f;
            sc = g_scale[g * 64 + f];
            sh = g_shift[g * 64 + f];
        }
        float v = out[r * 64 + f] * sc + sh + x[r * 64 + f];
        v = fmaxf(v, 0.f);
        demb[r * 64 + f] = v;
        s += v;
        mx = fmaxf(mx, v);
    }
    if (curg >= 0) {
        atomicAdd(&g_psum[curg * 64 + f], s);
        atomicMax(reinterpret_cast<int*>(&g_pmax[curg * 64 + f]), __float_as_int(mx));
    }
}

// ---------------- flat output: [G, 2F] -----------------------------------------
__global__ void k_flat(float* __restrict__ flat) {
    int idx = blockIdx.x * blockDim.x + threadIdx.x;
    if (idx >= G * 2 * F) return;
    int g = idx >> 7, j = idx & 127;
    float cnt = fmaxf(g_cnt[g], 1.f);
    flat[idx] = (j < 64) ? (g_psum[g * 64 + j] / cnt) : g_pmax[g * 64 + (j - 64)];
}

// ---------------- launch --------------------------------------------------------
extern "C" void kernel_launch(void* const* d_in, const int* in_sizes, int n_in,
                              void* d_out, int out_size) {
    const float* x     = (const float*)d_in[0];
    const int*   ei    = (const int*)d_in[1];
    const int*   batch = (const int*)d_in[2];
    const float* ew    = (const float*)d_in[3];
    const float* W     = (const float*)d_in[4];
    const float* bias  = (const float*)d_in[5];
    const float* gn_w  = (const float*)d_in[6];
    const float* gn_b  = (const float*)d_in[7];
    const float* gn_ms = (const float*)d_in[8];

    float* demb = (float*)d_out;
    float* flat = (float*)d_out + (size_t)NN * F;

    const int* src = ei;
    const int* dst = ei + NE;

    float *ph1, *ph2, *ph3, *pout;
    cudaGetSymbolAddress((void**)&ph1, g_h1);
    cudaGetSymbolAddress((void**)&ph2, g_h2);
    cudaGetSymbolAddress((void**)&ph3, g_h3);
    cudaGetSymbolAddress((void**)&pout, g_out);

    static bool attr_set = false;
    if (!attr_set) {
        cudaFuncSetAttribute(k_mat4, cudaFuncAttributeMaxDynamicSharedMemorySize, 90112);
        attr_set = true;
    }

    k_zero<<<256, 256>>>();
    k_deg<<<(NE + 255) / 256, 256>>>(dst, ew);
    k_dis<<<(NN + 255) / 256, 256>>>();
    k_scan1<<<NSCB, SCAN_B>>>();
    k_scan2<<<1, 256>>>();
    k_scan3<<<(NN + 255) / 256, 256>>>();
    k_scatter<<<(NE + 255) / 256, 256>>>(src, dst, ew);

    int gat_blocks = (NN * 16 + 255) / 256;
    k_gather<<<gat_blocks, 256>>>((const float4*)x,   (float4*)ph1);
    k_gather<<<gat_blocks, 256>>>((const float4*)ph1, (float4*)ph2);
    k_gather<<<gat_blocks, 256>>>((const float4*)ph2, (float4*)ph3);

    int mat_blocks = (NN + 63) / 64;
    size_t smem = (4 * 4096 + 4 * 16 * SX_STRIDE) * sizeof(float);
    k_mat4<<<mat_blocks, 256, smem>>>(x, ph1, ph2, ph3, W, bias, pout);

    int row_blocks = (NN + 255) / 256;
    k_stats<<<row_blocks, 256>>>(pout, batch);
    k_prep<<<(G * F + 255) / 256, 256>>>(gn_w, gn_b, gn_ms);
    k_final<<<row_blocks, 256>>>(pout, x, batch, demb);
    k_flat<<<(G * 2 * F + 255) / 256, 256>>>(flat);
}

// round 3
// speedup vs baseline: 1.7846x; 1.3093x over previous
#include <cuda_runtime.h>
#include <cuda_bf16.h>

#define NN 100000
#define NE 1600000
#define F 64
#define G 64
#define EPS 1e-5f
#define SCAN_B 512
#define NSCB ((NN + SCAN_B - 1) / SCAN_B)   // 196

// ---------------- scratch (device globals) ----------------------------------
__device__ float2 g_degcnt[NN];            // .x = weighted deg, .y = count (float)
__device__ float g_dis[NN];
__device__ int   g_scan[NN];
__device__ int2  g_rowinfo[NN];            // {start, count}
__device__ int   g_cursor[NN];
__device__ int   g_bsum[NSCB];
__device__ int   g_boff[NSCB];
__device__ unsigned long long g_csr[NE];   // low32 = src idx, high32 = norm bits
__device__ float g_h1[NN * F];
__device__ float g_h2[NN * F];
__device__ float g_h3[NN * F];
__device__ float g_out[NN * F];
__device__ float g_sum[G * F];
__device__ float g_sumsq[G * F];
__device__ float g_cnt[G];
__device__ float g_scale[G * F];
__device__ float g_shift[G * F];
__device__ float g_psum[G * F];
__device__ float g_pmax[G * F];

// ---------------- f32x2 packed helpers ---------------------------------------
__device__ __forceinline__ void fma2(unsigned long long& d, unsigned long long a,
                                     unsigned long long b) {
    asm("fma.rn.f32x2 %0, %1, %2, %0;" : "+l"(d) : "l"(a), "l"(b));
}
__device__ __forceinline__ unsigned long long pack2(float a) {
    unsigned long long p;
    asm("mov.b64 %0, {%1, %1};" : "=l"(p) : "f"(a));
    return p;
}

// ---------------- zero small scratch ------------------------------------------
__global__ void k_zero() {
    int i = blockIdx.x * blockDim.x + threadIdx.x;
    int st = gridDim.x * blockDim.x;
    for (int j = i; j < NN; j += st) g_degcnt[j] = make_float2(0.f, 0.f);
    for (int j = i; j < G * F; j += st) { g_sum[j] = 0.f; g_sumsq[j] = 0.f; g_psum[j] = 0.f; g_pmax[j] = 0.f; }
    for (int j = i; j < G; j += st) g_cnt[j] = 0.f;
}

// ---------------- weighted degree + in-degree count (one float2 atomic) ------
__global__ void k_deg(const int* __restrict__ dst, const float* __restrict__ w) {
    int e = blockIdx.x * blockDim.x + threadIdx.x;
    if (e < NE) {
        atomicAdd(&g_degcnt[dst[e]], make_float2(w[e], 1.f));
    }
}

// ---------------- prefix scan of counts ---------------------------------------
__global__ void k_scan1() {
    __shared__ int s[SCAN_B];
    int tid = threadIdx.x;
    int i = blockIdx.x * SCAN_B + tid;
    int v = (i < NN) ? (int)g_degcnt[i].y : 0;
    s[tid] = v;
    __syncthreads();
    for (int off = 1; off < SCAN_B; off <<= 1) {
        int t = (tid >= off) ? s[tid - off] : 0;
        __syncthreads();
        s[tid] += t;
        __syncthreads();
    }
    if (i < NN) g_scan[i] = s[tid] - v;       // exclusive
    if (tid == SCAN_B - 1) g_bsum[blockIdx.x] = s[tid];
}

__global__ void k_scan2() {
    __shared__ int s[256];
    int tid = threadIdx.x;
    int v = (tid < NSCB) ? g_bsum[tid] : 0;
    s[tid] = v;
    __syncthreads();
    for (int off = 1; off < 256; off <<= 1) {
        int t = (tid >= off) ? s[tid - off] : 0;
        __syncthreads();
        s[tid] += t;
        __syncthreads();
    }
    if (tid < NSCB) g_boff[tid] = s[tid] - v; // exclusive
}

// scan fixup + fused deg^{-1/2}
__global__ void k_scan3dis() {
    int i = blockIdx.x * blockDim.x + threadIdx.x;
    if (i < NN) {
        float2 dc = g_degcnt[i];
        int c = (int)dc.y;
        int v = g_scan[i] + g_boff[i >> 9];
        g_rowinfo[i] = make_int2(v, c);
        g_cursor[i] = v;
        g_dis[i] = dc.x > 0.f ? rsqrtf(dc.x) : 0.f;
    }
}

// ---------------- scatter edges into CSR with fused norm -----------------------
__global__ void k_scatter(const int* __restrict__ src, const int* __restrict__ dst,
                          const float* __restrict__ w) {
    int e = blockIdx.x * blockDim.x + threadIdx.x;
    if (e >= NE) return;
    int s = src[e];
    int d = dst[e];
    float nw = g_dis[s] * w[e] * g_dis[d];
    int p = atomicAdd(&g_cursor[d], 1);
    g_csr[p] = ((unsigned long long)__float_as_uint(nw) << 32) | (unsigned)s;
}

// ---------------- gather hop: hcur[n] = sum_e norm_e * hprev[src_e] ------------
// 16 threads per node, one float4 lane each. Unroll 8 for MLP.
__global__ void k_gather(const float4* __restrict__ hprev, float4* __restrict__ hcur) {
    int gid = blockIdx.x * blockDim.x + threadIdx.x;
    int n = gid >> 4;
    int q = gid & 15;
    if (n >= NN) return;
    int2 ri = g_rowinfo[n];
    int e = ri.x;
    int end = e + ri.y;
    float4 acc = make_float4(0.f, 0.f, 0.f, 0.f);
    for (; e + 8 <= end; e += 8) {
        unsigned long long r[8];
        #pragma unroll
        for (int j = 0; j < 8; j++) r[j] = g_csr[e + j];
        float4 v[8];
        #pragma unroll
        for (int j = 0; j < 8; j++) v[j] = hprev[(int)(r[j] & 0xffffffffu) * 16 + q];
        #pragma unroll
        for (int j = 0; j < 8; j++) {
            float w = __uint_as_float((unsigned)(r[j] >> 32));
            acc.x = fmaf(w, v[j].x, acc.x); acc.y = fmaf(w, v[j].y, acc.y);
            acc.z = fmaf(w, v[j].z, acc.z); acc.w = fmaf(w, v[j].w, acc.w);
        }
    }
    for (; e + 4 <= end; e += 4) {
        unsigned long long r[4];
        #pragma unroll
        for (int j = 0; j < 4; j++) r[j] = g_csr[e + j];
        float4 v[4];
        #pragma unroll
        for (int j = 0; j < 4; j++) v[j] = hprev[(int)(r[j] & 0xffffffffu) * 16 + q];
        #pragma unroll
        for (int j = 0; j < 4; j++) {
            float w = __uint_as_float((unsigned)(r[j] >> 32));
            acc.x = fmaf(w, v[j].x, acc.x); acc.y = fmaf(w, v[j].y, acc.y);
            acc.z = fmaf(w, v[j].z, acc.z); acc.w = fmaf(w, v[j].w, acc.w);
        }
    }
    for (; e < end; e++) {
        unsigned long long r0 = g_csr[e];
        float4 v0 = hprev[(int)(r0 & 0xffffffffu) * 16 + q];
        float w0 = __uint_as_float((unsigned)(r0 >> 32));
        acc.x = fmaf(w0, v0.x, acc.x); acc.y = fmaf(w0, v0.y, acc.y);
        acc.z = fmaf(w0, v0.z, acc.z); acc.w = fmaf(w0, v0.w, acc.w);
    }
    hcur[n * 16 + q] = acc;
}

// ---------------- fused 4-way matmul via packed FFMA2 --------------------------
// 512 threads, 256 rows/block. Thread: f8 = tid&7 (16 cols = 8 f32x2),
// rg = tid>>3 (0..63), rows rg*4 .. rg*4+3. acc[4 rows][4 u64].
#define SX_STRIDE 68
#define MAT_ROWS 256
__global__ void __launch_bounds__(512) k_mat4(
        const float* __restrict__ X0, const float* __restrict__ X1,
        const float* __restrict__ X2, const float* __restrict__ X3,
        const float* __restrict__ W, const float* __restrict__ bias,
        float* __restrict__ out) {
    extern __shared__ float sm[];
    float* sW = sm;                        // 4*4096 floats = 64KB
    float* sX = sm + 4 * 4096;             // 256*68 floats
    int tid = threadIdx.x;

    // load 4 weight matrices
    const float4* W4 = (const float4*)W;
    float4* sW4 = (float4*)sW;
    #pragma unroll
    for (int i = 0; i < 8; i++) sW4[tid + i * 512] = W4[tid + i * 512];

    int f8 = tid & 7;            // 8 threads span 64 cols (8 floats each)
    int rg = tid >> 3;           // 0..63, 4 rows each
    int base = blockIdx.x * MAT_ROWS;
    const float* Xs[4] = {X0, X1, X2, X3};

    // init acc with bias (packed)
    unsigned long long acc[4][4];
    {
        ulonglong2 b0 = *reinterpret_cast<const ulonglong2*>(bias + f8 * 8);
        ulonglong2 b1 = *reinterpret_cast<const ulonglong2*>(bias + f8 * 8 + 4);
        #pragma unroll
        for (int r = 0; r < 4; r++) {
            acc[r][0] = b0.x; acc[r][1] = b0.y; acc[r][2] = b1.x; acc[r][3] = b1.y;
        }
    }

    for (int m = 0; m < 4; m++) {
        // stage Xm tile: 256 rows x 16 float4 = 4096 float4, 8 per thread
        __syncthreads();
        const float4* Xm4 = (const float4*)Xs[m];
        #pragma unroll
        for (int i = 0; i < 8; i++) {
            int idx = tid + i * 512;
            int rl = idx >> 4;
            int fq = idx & 15;
            int grow = base + rl;
            float4 v = (grow < NN) ? Xm4[grow * 16 + fq]
                                   : make_float4(0.f, 0.f, 0.f, 0.f);
            *reinterpret_cast<float4*>(&sX[rl * SX_STRIDE + fq * 4]) = v;
        }
        __syncthreads();

        const float* wbase = sW + m * 4096 + f8 * 8;
        #pragma unroll 4
        for (int k4 = 0; k4 < 64; k4 += 4) {
            float4 a4[4];
            #pragma unroll
            for (int r = 0; r < 4; r++)
                a4[r] = *reinterpret_cast<const float4*>(&sX[(rg * 4 + r) * SX_STRIDE + k4]);
            #pragma unroll
            for (int kk = 0; kk < 4; kk++) {
                ulonglong2 w0 = *reinterpret_cast<const ulonglong2*>(wbase + (k4 + kk) * 64);
                ulonglong2 w1 = *reinterpret_cast<const ulonglong2*>(wbase + (k4 + kk) * 64 + 4);
                #pragma unroll
                for (int r = 0; r < 4; r++) {
                    float av = (kk == 0) ? a4[r].x : (kk == 1) ? a4[r].y
                             : (kk == 2) ? a4[r].z : a4[r].w;
                    unsigned long long p = pack2(av);
                    fma2(acc[r][0], p, w0.x);
                    fma2(acc[r][1], p, w0.y);
                    fma2(acc[r][2], p, w1.x);
                    fma2(acc[r][3], p, w1.y);
                }
            }
        }
    }

    #pragma unroll
    for (int r = 0; r < 4; r++) {
        int grow = base + rg * 4 + r;
        if (grow < NN) {
            ulonglong2* o = reinterpret_cast<ulonglong2*>(out + grow * 64 + f8 * 8);
            o[0] = make_ulonglong2(acc[r][0], acc[r][1]);
            o[1] = make_ulonglong2(acc[r][2], acc[r][3]);
        }
    }
}

// ---------------- GraphNorm stats ----------------------------------------------
__global__ void k_stats(const float* __restrict__ out, const int* __restrict__ batch) {
    int f = threadIdx.x & 63;
    int rg = threadIdx.x >> 6;
    int row0 = blockIdx.x * 256;
    int rend = min(row0 + 256, NN);
    float s = 0.f, sq = 0.f, c = 0.f;
    int curg = -1;
    for (int r = row0 + rg; r < rend; r += 4) {
        int g = batch[r];
        if (g != curg) {
            if (curg >= 0) {
                atomicAdd(&g_sum[curg * 64 + f], s);
                atomicAdd(&g_sumsq[curg * 64 + f], sq);
                if (f == 0) atomicAdd(&g_cnt[curg], c);
            }
            curg = g; s = 0.f; sq = 0.f; c = 0.f;
        }
        float v = out[r * 64 + f];
        s += v; sq += v * v; c += 1.f;
    }
    if (curg >= 0) {
        atomicAdd(&g_sum[curg * 64 + f], s);
        atomicAdd(&g_sumsq[curg * 64 + f], sq);
        if (f == 0) atomicAdd(&g_cnt[curg], c);
    }
}

// ---------------- per-(g,f) scale/shift ------------------------------------------
__global__ void k_prep(const float* __restrict__ gn_w, const float* __restrict__ gn_b,
                       const float* __restrict__ gn_ms) {
    int idx = blockIdx.x * blockDim.x + threadIdx.x;
    if (idx >= G * F) return;
    int g = idx >> 6, f = idx & 63;
    float cnt = fmaxf(g_cnt[g], 1.f);
    float m = g_sum[idx] / cnt;
    float ms = m * gn_ms[f];
    float var = g_sumsq[idx] / cnt - ms * (2.f * m - ms);
    var = fmaxf(var, 0.f);
    float sc = gn_w[f] * rsqrtf(var + EPS);
    g_scale[idx] = sc;
    g_shift[idx] = gn_b[f] - ms * sc;
}

// ---------------- normalize + residual + relu + pooling ---------------------------
__global__ void k_final(const float* __restrict__ out, const float* __restrict__ x,
                        const int* __restrict__ batch, float* __restrict__ demb) {
    int f = threadIdx.x & 63;
    int rg = threadIdx.x >> 6;
    int row0 = blockIdx.x * 256;
    int rend = min(row0 + 256, NN);
    float s = 0.f, mx = 0.f;
    int curg = -1;
    float sc = 0.f, sh = 0.f;
    for (int r = row0 + rg; r < rend; r += 4) {
        int g = batch[r];
        if (g != curg) {
            if (curg >= 0) {
                atomicAdd(&g_psum[curg * 64 + f], s);
                atomicMax(reinterpret_cast<int*>(&g_pmax[curg * 64 + f]), __float_as_int(mx));
            }
            curg = g; s = 0.f; mx = 0.f;
            sc = g_scale[g * 64 + f];
            sh = g_shift[g * 64 + f];
        }
        float v = out[r * 64 + f] * sc + sh + x[r * 64 + f];
        v = fmaxf(v, 0.f);
        demb[r * 64 + f] = v;
        s += v;
        mx = fmaxf(mx, v);
    }
    if (curg >= 0) {
        atomicAdd(&g_psum[curg * 64 + f], s);
        atomicMax(reinterpret_cast<int*>(&g_pmax[curg * 64 + f]), __float_as_int(mx));
    }
}

// ---------------- flat output: [G, 2F] ---------------------------------------------
__global__ void k_flat(float* __restrict__ flat) {
    int idx = blockIdx.x * blockDim.x + threadIdx.x;
    if (idx >= G * 2 * F) return;
    int g = idx >> 7, j = idx & 127;
    float cnt = fmaxf(g_cnt[g], 1.f);
    flat[idx] = (j < 64) ? (g_psum[g * 64 + j] / cnt) : g_pmax[g * 64 + (j - 64)];
}

// ---------------- launch -------------------------------------------------------------
extern "C" void kernel_launch(void* const* d_in, const int* in_sizes, int n_in,
                              void* d_out, int out_size) {
    const float* x     = (const float*)d_in[0];
    const int*   ei    = (const int*)d_in[1];
    const int*   batch = (const int*)d_in[2];
    const float* ew    = (const float*)d_in[3];
    const float* W     = (const float*)d_in[4];
    const float* bias  = (const float*)d_in[5];
    const float* gn_w  = (const float*)d_in[6];
    const float* gn_b  = (const float*)d_in[7];
    const float* gn_ms = (const float*)d_in[8];

    float* demb = (float*)d_out;
    float* flat = (float*)d_out + (size_t)NN * F;

    const int* src = ei;
    const int* dst = ei + NE;

    float *ph1, *ph2, *ph3, *pout;
    cudaGetSymbolAddress((void**)&ph1, g_h1);
    cudaGetSymbolAddress((void**)&ph2, g_h2);
    cudaGetSymbolAddress((void**)&ph3, g_h3);
    cudaGetSymbolAddress((void**)&pout, g_out);

    size_t smem = (4 * 4096 + MAT_ROWS * SX_STRIDE) * sizeof(float);  // 135168
    cudaFuncSetAttribute(k_mat4, cudaFuncAttributeMaxDynamicSharedMemorySize, (int)smem);

    k_zero<<<256, 256>>>();
    k_deg<<<(NE + 255) / 256, 256>>>(dst, ew);
    k_scan1<<<NSCB, SCAN_B>>>();
    k_scan2<<<1, 256>>>();
    k_scan3dis<<<(NN + 255) / 256, 256>>>();
    k_scatter<<<(NE + 255) / 256, 256>>>(src, dst, ew);

    int gat_blocks = (NN * 16 + 255) / 256;
    k_gather<<<gat_blocks, 256>>>((const float4*)x,   (float4*)ph1);
    k_gather<<<gat_blocks, 256>>>((const float4*)ph1, (float4*)ph2);
    k_gather<<<gat_blocks, 256>>>((const float4*)ph2, (float4*)ph3);

    int mat_blocks = (NN + MAT_ROWS - 1) / MAT_ROWS;
    k_mat4<<<mat_blocks, 512, smem>>>(x, ph1, ph2, ph3, W, bias, pout);

    int row_blocks = (NN + 255) / 256;
    k_stats<<<row_blocks, 256>>>(pout, batch);
    k_prep<<<(G * F + 255) / 256, 256>>>(gn_w, gn_b, gn_ms);
    k_final<<<row_blocks, 256>>>(pout, x, batch, demb);
    k_flat<<<(G * 2 * F + 255) / 256, 256>>>(flat);
}